// round 1
// baseline (speedup 1.0000x reference)
#include <cuda_runtime.h>
#include <cuda_bf16.h>

#define WIN 48
#define BK  256
#define HALO (WIN - 1)          // 47
#define TILE (BK + HALO)        // 303 rows staged per block

// Scratch for per-window coefficients: {beta_r, beta_g, beta_b, gamma} per window k.
// N is fixed at 400000 in this problem; size with headroom. __device__ global = allowed scratch.
__device__ float4 g_beta[420000];

// Kernel 1: for each window k, compute m_c (channel means), unbiased-variance
// ratio alpha = std0/std1 (computed as sqrt(q0/q1) with direct centered sums —
// no moment cancellation), and the affine coefficients beta_c(k), gamma(k).
__global__ __launch_bounds__(BK) void pos_beta_kernel(const float* __restrict__ x,
                                                      const float* __restrict__ Wm,
                                                      int N, int K) {
    __shared__ float4 sx[TILE];
    const int k0 = blockIdx.x * BK;

    // Stage rows k0 .. k0+TILE-1 as float4 (w unused) -> conflict-free LDS.128 later.
    for (int i = threadIdx.x; i < TILE; i += BK) {
        const int r = k0 + i;
        float4 v = make_float4(0.f, 0.f, 0.f, 0.f);
        if (r < N) {
            v.x = x[3 * r + 0];
            v.y = x[3 * r + 1];
            v.z = x[3 * r + 2];
        }
        sx[i] = v;
    }
    __syncthreads();

    const int k = k0 + threadIdx.x;
    if (k >= K) return;

    // Projection matrix (broadcast loads, L1-resident).
    const float W00 = Wm[0], W01 = Wm[1], W02 = Wm[2];
    const float W10 = Wm[3], W11 = Wm[4], W12 = Wm[5];
    const float r0 = W00 + W01 + W02;   // mean of S0 sans bias (bias cancels everywhere)
    const float r1 = W10 + W11 + W12;

    // Pass 1: channel sums over the 48-row window.
    float sr = 0.f, sg = 0.f, sb = 0.f;
#pragma unroll
    for (int w = 0; w < WIN; ++w) {
        const float4 v = sx[threadIdx.x + w];
        sr += v.x; sg += v.y; sb += v.z;
    }
    const float imr = 48.f / sr;   // 1 / m_r
    const float img = 48.f / sg;
    const float imb = 48.f / sb;

    // Pass 2: direct centered second moments of S0, S1 (mean is exactly r_o).
    const float a0r = W00 * imr, a0g = W01 * img, a0b = W02 * imb;
    const float a1r = W10 * imr, a1g = W11 * img, a1b = W12 * imb;
    float q0 = 0.f, q1 = 0.f;
#pragma unroll
    for (int w = 0; w < WIN; ++w) {
        const float4 v = sx[threadIdx.x + w];
        const float u = fmaf(a0r, v.x, fmaf(a0g, v.y, fmaf(a0b, v.z, -r0)));
        const float s = fmaf(a1r, v.x, fmaf(a1g, v.y, fmaf(a1b, v.z, -r1)));
        q0 = fmaf(u, u, q0);
        q1 = fmaf(s, s, q1);
    }
    // alpha = std0/std1 (ddof=1 factors cancel in the ratio).
    const float alpha = sqrtf(q0 / q1);

    float4 out;
    out.x = fmaf(alpha, W10, W00) * imr;   // beta_r
    out.y = fmaf(alpha, W11, W01) * img;   // beta_g
    out.z = fmaf(alpha, W12, W02) * imb;   // beta_b
    out.w = fmaf(alpha, r1, r0);           // gamma
    g_beta[k] = out;
}

// Kernel 2: H[n] = x_r[n]*B_r(n) + x_g[n]*B_g(n) + x_b[n]*B_b(n) - G(n),
// where B/G are 48-wide sliding sums of beta/gamma over valid k in [max(0,n-47), min(n, K-1)].
// Out-of-range k are staged as zeros so the inner loop needs no clamping.
__global__ __launch_bounds__(BK) void pos_oadd_kernel(const float* __restrict__ x,
                                                      float* __restrict__ H,
                                                      int N, int K) {
    __shared__ float4 sb[TILE];
    const int n0 = blockIdx.x * BK;
    const int base = n0 - HALO;   // k for smem index 0

    for (int i = threadIdx.x; i < TILE; i += BK) {
        const int kk = base + i;
        sb[i] = (kk >= 0 && kk < K) ? g_beta[kk] : make_float4(0.f, 0.f, 0.f, 0.f);
    }
    __syncthreads();

    const int n = n0 + threadIdx.x;
    if (n >= N) return;

    float Br = 0.f, Bg = 0.f, Bb = 0.f, G = 0.f;
#pragma unroll
    for (int w = 0; w < WIN; ++w) {
        const float4 v = sb[threadIdx.x + w];
        Br += v.x; Bg += v.y; Bb += v.z; G += v.w;
    }

    const float xr = x[3 * n + 0];
    const float xg = x[3 * n + 1];
    const float xb = x[3 * n + 2];
    H[n] = fmaf(xr, Br, fmaf(xg, Bg, fmaf(xb, Bb, -G)));
}

extern "C" void kernel_launch(void* const* d_in, const int* in_sizes, int n_in,
                              void* d_out, int out_size) {
    const float* x  = (const float*)d_in[0];   // rgbs [1, N, 3]
    const float* Wm = (const float*)d_in[1];   // W [2,3]
    // d_in[2] = bias b [2]: cancels exactly in the math (h is window-mean-centered).

    const int N = in_sizes[0] / 3;
    const int K = N - WIN;
    float* H = (float*)d_out;

    if (K > 0) {
        const int g1 = (K + BK - 1) / BK;
        pos_beta_kernel<<<g1, BK>>>(x, Wm, N, K);
    }
    const int g2 = (N + BK - 1) / BK;
    pos_oadd_kernel<<<g2, BK>>>(x, H, N, K);
}

// round 2
// speedup vs baseline: 2.3028x; 2.3028x over previous
#include <cuda_runtime.h>
#include <cuda_bf16.h>

#define WIN  48
#define HALO (WIN - 1)          // 47
#define BK   128                // threads per block
#define CH   7                  // consecutive windows per thread (odd -> conflict-free SoA)
#define WPB  (BK * CH)          // 896 windows/outputs per block
#define TILE (WPB + HALO)       // 943 rows staged per block

// Scratch: per-window affine coefficients {beta_r, beta_g, beta_b, gamma}.
__device__ float4 g_beta[420000];

// ---------------------------------------------------------------------------
// Kernel 1: per window k, rolling 9-moment sums -> channel means, unbiased
// variance ratio alpha = std0/std1 via quadratic forms, affine coeffs beta/gamma.
// ---------------------------------------------------------------------------
__global__ __launch_bounds__(BK) void pos_beta_kernel(const float* __restrict__ x,
                                                      const float* __restrict__ Wm,
                                                      int N, int K) {
    __shared__ float sxr[TILE], sxg[TILE], sxb[TILE];
    const int k0 = blockIdx.x * WPB;

    for (int i = threadIdx.x; i < TILE; i += BK) {
        const int r = k0 + i;
        float a = 0.f, b = 0.f, c = 0.f;
        if (r < N) { a = x[3 * r]; b = x[3 * r + 1]; c = x[3 * r + 2]; }
        sxr[i] = a; sxg[i] = b; sxb[i] = c;
    }
    __syncthreads();

    const float W00 = Wm[0], W01 = Wm[1], W02 = Wm[2];
    const float W10 = Wm[3], W11 = Wm[4], W12 = Wm[5];
    const float r0 = W00 + W01 + W02;   // window-mean of S0 (bias cancels)
    const float r1 = W10 + W11 + W12;

    const int kl = threadIdx.x * CH;    // local index of this thread's first window

    // Initial 48-row accumulation of 9 moments.
    float Sx = 0.f, Sy = 0.f, Sz = 0.f;
    float Mxx = 0.f, Myy = 0.f, Mzz = 0.f, Mxy = 0.f, Mxz = 0.f, Myz = 0.f;
#pragma unroll
    for (int w = 0; w < WIN; ++w) {
        const float X = sxr[kl + w], Y = sxg[kl + w], Z = sxb[kl + w];
        Sx += X; Sy += Y; Sz += Z;
        Mxx = fmaf(X, X, Mxx); Myy = fmaf(Y, Y, Myy); Mzz = fmaf(Z, Z, Mzz);
        Mxy = fmaf(X, Y, Mxy); Mxz = fmaf(X, Z, Mxz); Myz = fmaf(Y, Z, Myz);
    }

#pragma unroll
    for (int j = 0; j < CH; ++j) {
        const int k = k0 + kl + j;
        if (k < K) {
            const float imr = __fdividef(48.f, Sx);   // 1/m_r
            const float img = __fdividef(48.f, Sy);
            const float imb = __fdividef(48.f, Sz);
            const float a0r = W00 * imr, a0g = W01 * img, a0b = W02 * imb;
            const float a1r = W10 * imr, a1g = W11 * img, a1b = W12 * imb;

            // q_o = sum_w (S_o - mean)^2 via quadratic form (mean of a.v is exactly r_o)
            const float q0 = a0r * a0r * Mxx + a0g * a0g * Myy + a0b * a0b * Mzz
                           + 2.f * (a0r * a0g * Mxy + a0r * a0b * Mxz + a0g * a0b * Myz)
                           - 48.f * r0 * r0;
            const float q1 = a1r * a1r * Mxx + a1g * a1g * Myy + a1b * a1b * Mzz
                           + 2.f * (a1r * a1g * Mxy + a1r * a1b * Mxz + a1g * a1b * Myz)
                           - 48.f * r1 * r1;

            const float alpha = sqrtf(q0 / q1);   // ddof factors cancel in the ratio

            float4 out;
            out.x = fmaf(alpha, W10, W00) * imr;
            out.y = fmaf(alpha, W11, W01) * img;
            out.z = fmaf(alpha, W12, W02) * imb;
            out.w = fmaf(alpha, r1, r0);
            g_beta[k] = out;
        }
        if (j + 1 < CH) {
            const int ia = kl + j + WIN, is = kl + j;   // ia <= TILE-1 by construction
            const float Xn = sxr[ia], Yn = sxg[ia], Zn = sxb[ia];
            const float Xo = sxr[is], Yo = sxg[is], Zo = sxb[is];
            Sx += Xn - Xo; Sy += Yn - Yo; Sz += Zn - Zo;
            Mxx += fmaf(Xn, Xn, -Xo * Xo);
            Myy += fmaf(Yn, Yn, -Yo * Yo);
            Mzz += fmaf(Zn, Zn, -Zo * Zo);
            Mxy += fmaf(Xn, Yn, -Xo * Yo);
            Mxz += fmaf(Xn, Zn, -Xo * Zo);
            Myz += fmaf(Yn, Zn, -Yo * Zo);
        }
    }
}

// ---------------------------------------------------------------------------
// Kernel 2: H[n] = x.(48-wide sliding sum of beta) - sliding sum of gamma,
// with rolling sums over CH consecutive outputs per thread.
// ---------------------------------------------------------------------------
__global__ __launch_bounds__(BK) void pos_oadd_kernel(const float* __restrict__ x,
                                                      float* __restrict__ H,
                                                      int N, int K) {
    __shared__ float sbr[TILE], sbg[TILE], sbb[TILE], sgg[TILE];
    const int n0 = blockIdx.x * WPB;
    const int base = n0 - HALO;   // k for smem index 0 (zero-padded outside [0,K))

    for (int i = threadIdx.x; i < TILE; i += BK) {
        const int kk = base + i;
        float4 v = make_float4(0.f, 0.f, 0.f, 0.f);
        if (kk >= 0 && kk < K) v = g_beta[kk];
        sbr[i] = v.x; sbg[i] = v.y; sbb[i] = v.z; sgg[i] = v.w;
    }
    __syncthreads();

    const int nl = threadIdx.x * CH;

    float Br = 0.f, Bg = 0.f, Bb = 0.f, G = 0.f;
#pragma unroll
    for (int w = 0; w < WIN; ++w) {
        Br += sbr[nl + w]; Bg += sbg[nl + w]; Bb += sbb[nl + w]; G += sgg[nl + w];
    }

#pragma unroll
    for (int j = 0; j < CH; ++j) {
        const int n = n0 + nl + j;
        if (n < N) {
            const float xr = x[3 * n], xg = x[3 * n + 1], xb = x[3 * n + 2];
            H[n] = fmaf(xr, Br, fmaf(xg, Bg, fmaf(xb, Bb, -G)));
        }
        if (j + 1 < CH) {
            const int ia = nl + j + WIN, is = nl + j;
            Br += sbr[ia] - sbr[is];
            Bg += sbg[ia] - sbg[is];
            Bb += sbb[ia] - sbb[is];
            G  += sgg[ia] - sgg[is];
        }
    }
}

extern "C" void kernel_launch(void* const* d_in, const int* in_sizes, int n_in,
                              void* d_out, int out_size) {
    const float* x  = (const float*)d_in[0];   // rgbs [1, N, 3]
    const float* Wm = (const float*)d_in[1];   // W [2,3]
    // d_in[2] = bias: cancels exactly (h is window-mean-centered).

    const int N = in_sizes[0] / 3;
    const int K = N - WIN;
    float* H = (float*)d_out;

    if (K > 0) {
        const int g1 = (K + WPB - 1) / WPB;
        pos_beta_kernel<<<g1, BK>>>(x, Wm, N, K);
    }
    const int g2 = (N + WPB - 1) / WPB;
    pos_oadd_kernel<<<g2, BK>>>(x, H, N, K);
}

// round 3
// speedup vs baseline: 2.6102x; 1.1335x over previous
#include <cuda_runtime.h>
#include <cuda_bf16.h>

#define WIN  48
#define HALO 47
#define BK   256
#define CH   2
#define WPB  (BK * CH)        // 512 outputs per block
#define NB   (WPB + HALO)     // 559 betas per block (local k range)
#define TX   (NB + HALO)      // 606 x rows staged per block
#define RX   3                // scan chunk: 3*256 = 768 >= TX+1
#define RB   3                // 768 >= NB+1
#define XOFF 0.75f            // centering constant (exact algebra for any value)

// Block-wide exclusive scan of NCH channels held in registers.
// wt must hold >= 8*NCH floats of shared memory. All BK threads must call.
template<int NCH>
__device__ __forceinline__ void block_scan_excl(float (&v)[NCH], float* wt, int t) {
    const int lane = t & 31, w = t >> 5;
    float inc[NCH];
#pragma unroll
    for (int c = 0; c < NCH; ++c) inc[c] = v[c];
#pragma unroll
    for (int d = 1; d < 32; d <<= 1) {
#pragma unroll
        for (int c = 0; c < NCH; ++c) {
            const float u = __shfl_up_sync(0xffffffffu, inc[c], d);
            if (lane >= d) inc[c] += u;
        }
    }
    if (lane == 31) {
#pragma unroll
        for (int c = 0; c < NCH; ++c) wt[w * NCH + c] = inc[c];
    }
    __syncthreads();
    if (t < 8) {   // BK/32 = 8 warp totals
        float s[NCH];
#pragma unroll
        for (int c = 0; c < NCH; ++c) s[c] = wt[t * NCH + c];
#pragma unroll
        for (int d = 1; d < 8; d <<= 1) {
#pragma unroll
            for (int c = 0; c < NCH; ++c) {
                const float u = __shfl_up_sync(0x000000ffu, s[c], d);
                if (t >= d) s[c] += u;
            }
        }
#pragma unroll
        for (int c = 0; c < NCH; ++c) wt[t * NCH + c] = s[c];
    }
    __syncthreads();
#pragma unroll
    for (int c = 0; c < NCH; ++c) {
        const float base = (w > 0) ? wt[(w - 1) * NCH + c] : 0.f;
        v[c] = base + inc[c] - v[c];   // exclusive prefix for this thread's chunk
    }
}

__global__ __launch_bounds__(BK) void pos_fused_kernel(const float* __restrict__ x,
                                                       const float* __restrict__ Wm,
                                                       float* __restrict__ H,
                                                       int N, int K) {
    __shared__ float s_x[3][TX];            // centered rgb rows
    __shared__ float s_P[9 * (TX + 1)];     // 9 moment prefixes; later aliased by 4 beta prefixes
    __shared__ float s_vb[4][NB];           // beta values {br,bg,bb,gamma}
    __shared__ float s_wt[8 * 9];           // warp totals for scans

    const int t  = threadIdx.x;
    const int n0 = blockIdx.x * WPB;
    const int kb = n0 - HALO;               // global row index of local index 0

    // --- stage x rows (centered), zero-padded out of range ---
    for (int j = t; j < TX; j += BK) {
        const int r = kb + j;
        float a = 0.f, b = 0.f, c = 0.f;
        if (r >= 0 && r < N) {
            a = x[3 * r]     - XOFF;
            b = x[3 * r + 1] - XOFF;
            c = x[3 * r + 2] - XOFF;
        }
        s_x[0][j] = a; s_x[1][j] = b; s_x[2][j] = c;
    }
    __syncthreads();

    // --- prefix-scan 9 moment channels: y,yy pairs of centered data ---
    {
        float v[9];
#pragma unroll
        for (int c = 0; c < 9; ++c) v[c] = 0.f;
#pragma unroll
        for (int r = 0; r < RX; ++r) {
            const int i = t * RX + r;
            if (i < TX) {
                const float X = s_x[0][i], Y = s_x[1][i], Z = s_x[2][i];
                v[0] += X; v[1] += Y; v[2] += Z;
                v[3] = fmaf(X, X, v[3]); v[4] = fmaf(Y, Y, v[4]); v[5] = fmaf(Z, Z, v[5]);
                v[6] = fmaf(X, Y, v[6]); v[7] = fmaf(X, Z, v[7]); v[8] = fmaf(Y, Z, v[8]);
            }
        }
        block_scan_excl<9>(v, s_wt, t);
#pragma unroll
        for (int r = 0; r < RX; ++r) {
            const int i = t * RX + r;
            if (i <= TX) {
#pragma unroll
                for (int c = 0; c < 9; ++c) s_P[c * (TX + 1) + i] = v[c];
                if (i < TX) {
                    const float X = s_x[0][i], Y = s_x[1][i], Z = s_x[2][i];
                    v[0] += X; v[1] += Y; v[2] += Z;
                    v[3] = fmaf(X, X, v[3]); v[4] = fmaf(Y, Y, v[4]); v[5] = fmaf(Z, Z, v[5]);
                    v[6] = fmaf(X, Y, v[6]); v[7] = fmaf(X, Z, v[7]); v[8] = fmaf(Y, Z, v[8]);
                }
            }
        }
    }
    __syncthreads();

    // --- per-window beta/gamma via O(1) prefix lookups ---
    const float W00 = Wm[0], W01 = Wm[1], W02 = Wm[2];
    const float W10 = Wm[3], W11 = Wm[4], W12 = Wm[5];
    const float r0 = W00 + W01 + W02;
    const float r1 = W10 + W11 + W12;

#pragma unroll
    for (int c0 = 0; c0 < 3; ++c0) {       // 3*256 = 768 >= NB
        const int i = t + c0 * BK;
        if (i < NB) {
            const int k = kb + i;
            float br = 0.f, bg = 0.f, bb = 0.f, gg = 0.f;
            if (k >= 0 && k < K) {
#define PD(c) (s_P[(c) * (TX + 1) + i + WIN] - s_P[(c) * (TX + 1) + i])
                const float Sx  = PD(0), Sy  = PD(1), Sz  = PD(2);
                const float Mxx = PD(3), Myy = PD(4), Mzz = PD(5);
                const float Mxy = PD(6), Mxz = PD(7), Myz = PD(8);
#undef PD
                // m_c = (Sy_c + 48*XOFF)/48 ; im_c = 1/m_c
                const float imr = __fdividef(48.f, Sx + 48.f * XOFF);
                const float img = __fdividef(48.f, Sy + 48.f * XOFF);
                const float imb = __fdividef(48.f, Sz + 48.f * XOFF);
                const float a0r = W00 * imr, a0g = W01 * img, a0b = W02 * imb;
                const float a1r = W10 * imr, a1g = W11 * img, a1b = W12 * imb;
                // window mean of a.y (times 48)
                const float T0 = a0r * Sx + a0g * Sy + a0b * Sz;
                const float T1 = a1r * Sx + a1g * Sy + a1b * Sz;
                // q_o = sum_w (a.y_w)^2 - (T_o)^2/48  (shift-invariant variance)
                const float q0 = a0r * a0r * Mxx + a0g * a0g * Myy + a0b * a0b * Mzz
                               + 2.f * (a0r * a0g * Mxy + a0r * a0b * Mxz + a0g * a0b * Myz)
                               - T0 * T0 * (1.f / 48.f);
                const float q1 = a1r * a1r * Mxx + a1g * a1g * Myy + a1b * a1b * Mzz
                               + 2.f * (a1r * a1g * Mxy + a1r * a1b * Mxz + a1g * a1b * Myz)
                               - T1 * T1 * (1.f / 48.f);
                const float alpha = sqrtf(__fdividef(q0, q1));
                br = fmaf(alpha, W10, W00) * imr;
                bg = fmaf(alpha, W11, W01) * img;
                bb = fmaf(alpha, W12, W02) * imb;
                gg = fmaf(alpha, r1, r0);   // beta . m  (exact)
            }
            s_vb[0][i] = br; s_vb[1][i] = bg; s_vb[2][i] = bb; s_vb[3][i] = gg;
        }
    }
    __syncthreads();

    // --- prefix-scan 4 beta channels (prefix arrays alias dead s_P region) ---
    {
        float v[4];
#pragma unroll
        for (int c = 0; c < 4; ++c) v[c] = 0.f;
#pragma unroll
        for (int r = 0; r < RB; ++r) {
            const int i = t * RB + r;
            if (i < NB) {
#pragma unroll
                for (int c = 0; c < 4; ++c) v[c] += s_vb[c][i];
            }
        }
        block_scan_excl<4>(v, s_wt, t);
#pragma unroll
        for (int r = 0; r < RB; ++r) {
            const int i = t * RB + r;
            if (i <= NB) {
#pragma unroll
                for (int c = 0; c < 4; ++c) s_P[c * (NB + 1) + i] = v[c];
                if (i < NB) {
#pragma unroll
                    for (int c = 0; c < 4; ++c) v[c] += s_vb[c][i];
                }
            }
        }
    }
    __syncthreads();

    // --- outputs: H[n] = x[n] . slidingSum(beta) - slidingSum(gamma) ---
#pragma unroll
    for (int c0 = 0; c0 < CH; ++c0) {
        const int m = t + c0 * BK;
        const int n = n0 + m;
        if (n < N) {
            const float Br = s_P[0 * (NB + 1) + m + WIN] - s_P[0 * (NB + 1) + m];
            const float Bg = s_P[1 * (NB + 1) + m + WIN] - s_P[1 * (NB + 1) + m];
            const float Bb = s_P[2 * (NB + 1) + m + WIN] - s_P[2 * (NB + 1) + m];
            const float G  = s_P[3 * (NB + 1) + m + WIN] - s_P[3 * (NB + 1) + m];
            const float xr = x[3 * n], xg = x[3 * n + 1], xb = x[3 * n + 2];
            H[n] = fmaf(xr, Br, fmaf(xg, Bg, fmaf(xb, Bb, -G)));
        }
    }
}

extern "C" void kernel_launch(void* const* d_in, const int* in_sizes, int n_in,
                              void* d_out, int out_size) {
    const float* x  = (const float*)d_in[0];   // rgbs [1, N, 3]
    const float* Wm = (const float*)d_in[1];   // W [2,3]
    // d_in[2] = bias: cancels exactly (h is window-mean-centered).

    const int N = in_sizes[0] / 3;
    const int K = N - WIN;
    float* H = (float*)d_out;

    const int grid = (N + WPB - 1) / WPB;
    pos_fused_kernel<<<grid, BK>>>(x, Wm, H, N, K);
}

// round 4
// speedup vs baseline: 3.0877x; 1.1830x over previous
#include <cuda_runtime.h>
#include <cuda_bf16.h>

#define WIN  48
#define HALO 47
#define BK   256
#define CH   2
#define WPB  (BK * CH)        // 512 outputs per block
#define NB   (WPB + HALO)     // 559 betas per block
#define TX   (NB + HALO)      // 606 x rows staged per block
#define RX   3                // 3*256 = 768 >= TX+1
#define RB   3                // 768 >= NB+1
#define XOFF 0.75f            // centering constant (exact algebra)

// ---- shared memory layout (two aliased unions) ----
// union2: [ s_mp0 float4*(TX+1) | s_mp1 float4*(TX+1) | s_mp2 float*(TX+1) ]
//         s_bp (float4*(NB+1)) aliases s_mp0 after beta stage.
// union1: [ s_raw float*(3*TX) ]  aliased by s_vb (float4*NB) after x extraction.
#define U2_BYTES ((2 * (TX + 1) * 16 + (TX + 1) * 4 + 15) & ~15)   // 21856
#define U1_BYTES ((NB * 16 > 3 * TX * 4 ? NB * 16 : 3 * TX * 4))   // 8944
#define WT_OFF   (U2_BYTES + U1_BYTES)
#define SMEM_TOT (WT_OFF + 8 * 9 * 4)

// Block-wide exclusive scan of NCH register channels. wt >= 8*NCH floats.
template<int NCH>
__device__ __forceinline__ void block_scan_excl(float (&v)[NCH], float* wt, int t) {
    const int lane = t & 31, w = t >> 5;
    float inc[NCH];
#pragma unroll
    for (int c = 0; c < NCH; ++c) inc[c] = v[c];
#pragma unroll
    for (int d = 1; d < 32; d <<= 1) {
#pragma unroll
        for (int c = 0; c < NCH; ++c) {
            const float u = __shfl_up_sync(0xffffffffu, inc[c], d);
            if (lane >= d) inc[c] += u;
        }
    }
    if (lane == 31) {
#pragma unroll
        for (int c = 0; c < NCH; ++c) wt[w * NCH + c] = inc[c];
    }
    __syncthreads();
    if (t < 8) {
        float s[NCH];
#pragma unroll
        for (int c = 0; c < NCH; ++c) s[c] = wt[t * NCH + c];
#pragma unroll
        for (int d = 1; d < 8; d <<= 1) {
#pragma unroll
            for (int c = 0; c < NCH; ++c) {
                const float u = __shfl_up_sync(0x000000ffu, s[c], d);
                if (t >= d) s[c] += u;
            }
        }
#pragma unroll
        for (int c = 0; c < NCH; ++c) wt[t * NCH + c] = s[c];
    }
    __syncthreads();
#pragma unroll
    for (int c = 0; c < NCH; ++c) {
        const float base = (w > 0) ? wt[(w - 1) * NCH + c] : 0.f;
        v[c] = base + inc[c] - v[c];   // exclusive prefix at this thread's chunk start
    }
}

__global__ __launch_bounds__(BK) void pos_fused_kernel(const float* __restrict__ x,
                                                       const float* __restrict__ Wm,
                                                       float* __restrict__ H,
                                                       int N, int K) {
    __shared__ __align__(16) char smem[SMEM_TOT];
    float4* s_mp0 = (float4*)smem;                       // {Sx,Sy,Sz,Mxx} prefix
    float4* s_mp1 = s_mp0 + (TX + 1);                    // {Myy,Mzz,Mxy,Mxz}
    float*  s_mp2 = (float*)(s_mp1 + (TX + 1));          // Myz
    float4* s_bp  = (float4*)smem;                       // beta prefix (aliases s_mp0)
    float*  s_raw = (float*)(smem + U2_BYTES);           // centered x, AoS [3*TX]
    float4* s_vb  = (float4*)(smem + U2_BYTES);          // beta values (aliases s_raw)
    float*  s_wt  = (float*)(smem + WT_OFF);

    const int t  = threadIdx.x;
    const int n0 = blockIdx.x * WPB;
    const int kb = n0 - HALO;                            // global row of local index 0
    const int g0 = 3 * kb;

    // --- stage raw x (centered), coalesced stride-1; pad = 0 ---
    for (int e = t; e < 3 * TX; e += BK) {
        const int g = g0 + e;
        s_raw[e] = (g >= 0 && g < 3 * N) ? (x[g] - XOFF) : 0.f;
    }
    __syncthreads();

    // --- scan 9 moment channels over TX rows ---
    {
        float v[9];
#pragma unroll
        for (int c = 0; c < 9; ++c) v[c] = 0.f;
#pragma unroll
        for (int r = 0; r < RX; ++r) {
            const int i = t * RX + r;
            if (i < TX) {
                const float X = s_raw[3 * i], Y = s_raw[3 * i + 1], Z = s_raw[3 * i + 2];
                v[0] += X; v[1] += Y; v[2] += Z;
                v[3] = fmaf(X, X, v[3]); v[4] = fmaf(Y, Y, v[4]); v[5] = fmaf(Z, Z, v[5]);
                v[6] = fmaf(X, Y, v[6]); v[7] = fmaf(X, Z, v[7]); v[8] = fmaf(Y, Z, v[8]);
            }
        }
        block_scan_excl<9>(v, s_wt, t);
#pragma unroll
        for (int r = 0; r < RX; ++r) {
            const int i = t * RX + r;
            if (i <= TX) {
                s_mp0[i] = make_float4(v[0], v[1], v[2], v[3]);
                s_mp1[i] = make_float4(v[4], v[5], v[6], v[7]);
                s_mp2[i] = v[8];
                if (i < TX) {
                    const float X = s_raw[3 * i], Y = s_raw[3 * i + 1], Z = s_raw[3 * i + 2];
                    v[0] += X; v[1] += Y; v[2] += Z;
                    v[3] = fmaf(X, X, v[3]); v[4] = fmaf(Y, Y, v[4]); v[5] = fmaf(Z, Z, v[5]);
                    v[6] = fmaf(X, Y, v[6]); v[7] = fmaf(X, Z, v[7]); v[8] = fmaf(Y, Z, v[8]);
                }
            }
        }
    }
    __syncthreads();

    // --- extract this thread's output x values before s_raw is overwritten ---
    float xr[CH], xg[CH], xb[CH];
#pragma unroll
    for (int c0 = 0; c0 < CH; ++c0) {
        const int j = t + c0 * BK + HALO;   // local row of output m = t + c0*BK
        xr[c0] = s_raw[3 * j]     + XOFF;
        xg[c0] = s_raw[3 * j + 1] + XOFF;
        xb[c0] = s_raw[3 * j + 2] + XOFF;
    }
    __syncthreads();

    // --- per-window beta/gamma via O(1) prefix diffs; write s_vb (overlays s_raw) ---
    const float W00 = Wm[0], W01 = Wm[1], W02 = Wm[2];
    const float W10 = Wm[3], W11 = Wm[4], W12 = Wm[5];
    const float r0 = W00 + W01 + W02;
    const float r1 = W10 + W11 + W12;

#pragma unroll
    for (int c0 = 0; c0 < 3; ++c0) {
        const int i = t + c0 * BK;
        if (i < NB) {
            const int k = kb + i;
            float4 out = make_float4(0.f, 0.f, 0.f, 0.f);
            if (k >= 0 && k < K) {
                const float4 a0 = s_mp0[i], a1 = s_mp0[i + WIN];
                const float4 b0 = s_mp1[i], b1 = s_mp1[i + WIN];
                const float Sx  = a1.x - a0.x, Sy  = a1.y - a0.y, Sz  = a1.z - a0.z;
                const float Mxx = a1.w - a0.w;
                const float Myy = b1.x - b0.x, Mzz = b1.y - b0.y;
                const float Mxy = b1.z - b0.z, Mxz = b1.w - b0.w;
                const float Myz = s_mp2[i + WIN] - s_mp2[i];

                const float imr = __fdividef(48.f, Sx + 48.f * XOFF);
                const float img = __fdividef(48.f, Sy + 48.f * XOFF);
                const float imb = __fdividef(48.f, Sz + 48.f * XOFF);
                const float a0r = W00 * imr, a0g = W01 * img, a0b = W02 * imb;
                const float a1r = W10 * imr, a1g = W11 * img, a1b = W12 * imb;
                const float T0 = a0r * Sx + a0g * Sy + a0b * Sz;
                const float T1 = a1r * Sx + a1g * Sy + a1b * Sz;
                const float q0 = a0r * a0r * Mxx + a0g * a0g * Myy + a0b * a0b * Mzz
                               + 2.f * (a0r * a0g * Mxy + a0r * a0b * Mxz + a0g * a0b * Myz)
                               - T0 * T0 * (1.f / 48.f);
                const float q1 = a1r * a1r * Mxx + a1g * a1g * Myy + a1b * a1b * Mzz
                               + 2.f * (a1r * a1g * Mxy + a1r * a1b * Mxz + a1g * a1b * Myz)
                               - T1 * T1 * (1.f / 48.f);
                const float alpha = q0 * rsqrtf(q0 * q1);   // = sqrt(q0/q1)
                out.x = fmaf(alpha, W10, W00) * imr;
                out.y = fmaf(alpha, W11, W01) * img;
                out.z = fmaf(alpha, W12, W02) * imb;
                out.w = fmaf(alpha, r1, r0);                // beta . m (exact)
            }
            s_vb[i] = out;
        }
    }
    __syncthreads();

    // --- scan 4 beta channels; prefix s_bp overlays s_mp0 (dead now) ---
    {
        float v[4];
#pragma unroll
        for (int c = 0; c < 4; ++c) v[c] = 0.f;
#pragma unroll
        for (int r = 0; r < RB; ++r) {
            const int i = t * RB + r;
            if (i < NB) {
                const float4 b = s_vb[i];
                v[0] += b.x; v[1] += b.y; v[2] += b.z; v[3] += b.w;
            }
        }
        block_scan_excl<4>(v, s_wt, t);
#pragma unroll
        for (int r = 0; r < RB; ++r) {
            const int i = t * RB + r;
            if (i <= NB) {
                s_bp[i] = make_float4(v[0], v[1], v[2], v[3]);
                if (i < NB) {
                    const float4 b = s_vb[i];
                    v[0] += b.x; v[1] += b.y; v[2] += b.z; v[3] += b.w;
                }
            }
        }
    }
    __syncthreads();

    // --- outputs: H[n] = x[n] . slidingSum(beta) - slidingSum(gamma) ---
#pragma unroll
    for (int c0 = 0; c0 < CH; ++c0) {
        const int m = t + c0 * BK;
        const int n = n0 + m;
        if (n < N) {
            const float4 p0 = s_bp[m], p1 = s_bp[m + WIN];
            const float Br = p1.x - p0.x;
            const float Bg = p1.y - p0.y;
            const float Bb = p1.z - p0.z;
            const float G  = p1.w - p0.w;
            H[n] = fmaf(xr[c0], Br, fmaf(xg[c0], Bg, fmaf(xb[c0], Bb, -G)));
        }
    }
}

extern "C" void kernel_launch(void* const* d_in, const int* in_sizes, int n_in,
                              void* d_out, int out_size) {
    const float* x  = (const float*)d_in[0];   // rgbs [1, N, 3]
    const float* Wm = (const float*)d_in[1];   // W [2,3]
    // d_in[2] = bias: cancels exactly (h is window-mean-centered).

    const int N = in_sizes[0] / 3;
    const int K = N - WIN;
    float* H = (float*)d_out;

    const int grid = (N + WPB - 1) / WPB;
    pos_fused_kernel<<<grid, BK>>>(x, Wm, H, N, K);
}